// round 9
// baseline (speedup 1.0000x reference)
#include <cuda_runtime.h>
#include <math.h>

#define Bv    128
#define Dv    128
#define NMEM  200000
#define K1v   2048
#define INV_T (1.0f / 0.07f)

#define OUTS_ELEMS  (6LL * Bv * K1v)
#define MEM_ELEMS   ((long long)NMEM * Dv)
#define NIDX        (Bv * K1v)          // 262144
#define SLOTS       12
#define OVER_CAP    65536

// -------- device scratch (static zero-init == valid empty state) --------
__device__ int g_count[NMEM];                      // 0 at launch start
__device__ int g_owner[NMEM];                      // owner+1; 0 = no owner
__device__ int g_slots[(long long)NMEM * SLOTS];
__device__ int g_over [OVER_CAP];                  // 0 = empty, else ent+1
__device__ int g_nover;                            // allocator only

// ---------------------------------------------------------------------------
// Kernel 1: build inverse map + owner map. Scratch left zeroed by the
// previous launch's main kernel (static zero-init on first call).
// ---------------------------------------------------------------------------
__global__ void build_kernel(const int* __restrict__ idx,
                             const int* __restrict__ y)
{
    const int tid = blockIdx.x * blockDim.x + threadIdx.x;
    if (tid < NIDX) {
        const int row = idx[tid];
        const int pos = atomicAdd(&g_count[row], 1);
        if (pos < SLOTS) g_slots[(long long)row * SLOTS + pos] = tid;
        else {
            const int o = atomicAdd(&g_nover, 1);
            if (o < OVER_CAP) g_over[o] = tid + 1;
        }
    }
    // owner map: last occurrence of y wins (jnp .at[y].set semantics)
    if (tid < Bv) {
        const int yi = y[tid];
        bool last = true;
        for (int j = tid + 1; j < Bv; ++j)
            if (y[j] == yi) { last = false; break; }
        if (last) g_owner[yi] = tid + 1;
    }
}

// ---------------------------------------------------------------------------
// Kernel 2 (main): single streaming pass over all bank rows.
// One warp per row. Front batch: 4x LDG.128 + metadata + slot0 prefetch,
// all unconditional, before any branch or store. Self-clean at kernel END.
// ---------------------------------------------------------------------------
__global__ __launch_bounds__(256) void main_kernel(
    const float* __restrict__ l,
    const float* __restrict__ ab,
    const float* __restrict__ ori,
    const float* __restrict__ comp,
    const float* __restrict__ mem_l,
    const float* __restrict__ mem_ab,
    const float* __restrict__ mem_ori,
    const float* __restrict__ mem_comp,
    const int*   __restrict__ idx,
    float* __restrict__ outs,
    float* __restrict__ out_banks)
{
    const int warp = threadIdx.x >> 5;
    const int lane = threadIdx.x & 31;
    const long long gw = (long long)blockIdx.x * 8 + warp;   // 0..199999
    const long long r  = gw;

    // ---- front batch: all independent loads, no branches, no stores ----
    const float4 wl  = reinterpret_cast<const float4*>(mem_l    + r * Dv)[lane];
    const float4 wab = reinterpret_cast<const float4*>(mem_ab   + r * Dv)[lane];
    const float4 wor = reinterpret_cast<const float4*>(mem_ori  + r * Dv)[lane];
    const float4 wco = reinterpret_cast<const float4*>(mem_comp + r * Dv)[lane];

    const int ownerp1 = g_owner[r];
    const int cnt     = g_count[r];
    const int ent0    = g_slots[r * SLOTS];   // prefetch slot 0 (always valid)

    const int owner = ownerp1 - 1;

    // ---- write output banks: plain copy, or EMA-updated row ----
    if (owner < 0) {
        reinterpret_cast<float4*>(out_banks + 0 * MEM_ELEMS + r * Dv)[lane] = wl;
        reinterpret_cast<float4*>(out_banks + 1 * MEM_ELEMS + r * Dv)[lane] = wab;
        reinterpret_cast<float4*>(out_banks + 2 * MEM_ELEMS + r * Dv)[lane] = wor;
        reinterpret_cast<float4*>(out_banks + 3 * MEM_ELEMS + r * Dv)[lane] = wco;
    } else {
        const float* vsrc[4] = {l, ab, ori, comp};
        const float4 wsrc[4] = {wl, wab, wor, wco};
        #pragma unroll
        for (int m = 0; m < 4; ++m) {
            const float4 v = reinterpret_cast<const float4*>(vsrc[m] + owner * Dv)[lane];
            float4 p;
            p.x = wsrc[m].x * 0.5f + v.x * 0.5f;
            p.y = wsrc[m].y * 0.5f + v.y * 0.5f;
            p.z = wsrc[m].z * 0.5f + v.z * 0.5f;
            p.w = wsrc[m].w * 0.5f + v.w * 0.5f;
            float sq = p.x * p.x + p.y * p.y + p.z * p.z + p.w * p.w;
            #pragma unroll
            for (int off = 16; off > 0; off >>= 1)
                sq += __shfl_xor_sync(0xFFFFFFFFu, sq, off);
            const float inv = rsqrtf(sq);
            p.x *= inv; p.y *= inv; p.z *= inv; p.w *= inv;
            reinterpret_cast<float4*>(out_banks + (long long)m * MEM_ELEMS + r * Dv)[lane] = p;
        }
    }

    // ---- dot products for every (b,k) referencing this row ----
    const int nent = cnt < SLOTS ? cnt : SLOTS;
    for (int e = 0; e < nent; ++e) {
        const int ent = (e == 0) ? ent0 : g_slots[r * SLOTS + e];
        const int b   = ent >> 11;          // ent / K1v
        const int k   = ent & (K1v - 1);

        const float4 vl  = __ldg(reinterpret_cast<const float4*>(l    + b * Dv) + lane);
        const float4 vab = __ldg(reinterpret_cast<const float4*>(ab   + b * Dv) + lane);
        const float4 vor = __ldg(reinterpret_cast<const float4*>(ori  + b * Dv) + lane);
        const float4 vco = __ldg(reinterpret_cast<const float4*>(comp + b * Dv) + lane);

        float s0 = wor.x*vl.x  + wor.y*vl.y  + wor.z*vl.z  + wor.w*vl.w;
        float s1 = wl.x *vab.x + wl.y *vab.y + wl.z *vab.z + wl.w *vab.w;
        float s2 = wab.x*vor.x + wab.y*vor.y + wab.z*vor.z + wab.w*vor.w;
        float s3 = wco.x*vab.x + wco.y*vab.y + wco.z*vab.z + wco.w*vab.w;
        float s4 = wco.x*vl.x  + wco.y*vl.y  + wco.z*vl.z  + wco.w*vl.w;
        float s5 = wor.x*vco.x + wor.y*vco.y + wor.z*vco.z + wor.w*vco.w;

        #pragma unroll
        for (int off = 16; off > 0; off >>= 1) {
            s0 += __shfl_xor_sync(0xFFFFFFFFu, s0, off);
            s1 += __shfl_xor_sync(0xFFFFFFFFu, s1, off);
            s2 += __shfl_xor_sync(0xFFFFFFFFu, s2, off);
            s3 += __shfl_xor_sync(0xFFFFFFFFu, s3, off);
            s4 += __shfl_xor_sync(0xFFFFFFFFu, s4, off);
            s5 += __shfl_xor_sync(0xFFFFFFFFu, s5, off);
        }
        // butterfly leaves full sums in every lane: 6 parallel stores
        if (lane < 6) {
            const float sv = (lane == 0) ? s0 : (lane == 1) ? s1 :
                             (lane == 2) ? s2 : (lane == 3) ? s3 :
                             (lane == 4) ? s4 : s5;
            const long long base   = (long long)b * K1v + k;
            const long long stride = (long long)Bv * K1v;
            outs[lane * stride + base] = sv * INV_T;
        }
    }

    // ---- overflow entries (zero-sentinel; astronomically rare) ----
    if (gw < OVER_CAP) {
        const int e = g_over[gw];
        if (e != 0) {
            const int ent = e - 1;
            const int b   = ent >> 11;
            const int k   = ent & (K1v - 1);
            const long long row = idx[ent];

            const float4 ol  = reinterpret_cast<const float4*>(mem_l    + row * Dv)[lane];
            const float4 oab = reinterpret_cast<const float4*>(mem_ab   + row * Dv)[lane];
            const float4 oor = reinterpret_cast<const float4*>(mem_ori  + row * Dv)[lane];
            const float4 oco = reinterpret_cast<const float4*>(mem_comp + row * Dv)[lane];

            const float4 vl  = __ldg(reinterpret_cast<const float4*>(l    + b * Dv) + lane);
            const float4 vab = __ldg(reinterpret_cast<const float4*>(ab   + b * Dv) + lane);
            const float4 vor = __ldg(reinterpret_cast<const float4*>(ori  + b * Dv) + lane);
            const float4 vco = __ldg(reinterpret_cast<const float4*>(comp + b * Dv) + lane);

            float s0 = oor.x*vl.x  + oor.y*vl.y  + oor.z*vl.z  + oor.w*vl.w;
            float s1 = ol.x *vab.x + ol.y *vab.y + ol.z *vab.z + ol.w *vab.w;
            float s2 = oab.x*vor.x + oab.y*vor.y + oab.z*vor.z + oab.w*vor.w;
            float s3 = oco.x*vab.x + oco.y*vab.y + oco.z*vab.z + oco.w*vab.w;
            float s4 = oco.x*vl.x  + oco.y*vl.y  + oco.z*vl.z  + oco.w*vl.w;
            float s5 = oor.x*vco.x + oor.y*vco.y + oor.z*vco.z + oor.w*vco.w;

            #pragma unroll
            for (int off = 16; off > 0; off >>= 1) {
                s0 += __shfl_xor_sync(0xFFFFFFFFu, s0, off);
                s1 += __shfl_xor_sync(0xFFFFFFFFu, s1, off);
                s2 += __shfl_xor_sync(0xFFFFFFFFu, s2, off);
                s3 += __shfl_xor_sync(0xFFFFFFFFu, s3, off);
                s4 += __shfl_xor_sync(0xFFFFFFFFu, s4, off);
                s5 += __shfl_xor_sync(0xFFFFFFFFu, s5, off);
            }
            if (lane < 6) {
                const float sv = (lane == 0) ? s0 : (lane == 1) ? s1 :
                                 (lane == 2) ? s2 : (lane == 3) ? s3 :
                                 (lane == 4) ? s4 : s5;
                const long long base   = (long long)b * K1v + k;
                const long long stride = (long long)Bv * K1v;
                outs[lane * stride + base] = sv * INV_T;
            }
            if (lane == 0) g_over[gw] = 0;     // reset used sentinel
        }
    }

    // ---- self-clean for next launch (END of kernel: after all loads) ----
    if (lane == 0) {
        g_count[r] = 0;
        g_owner[r] = 0;
    }
    if (blockIdx.x == 0 && threadIdx.x == 0) g_nover = 0;
}

// ---------------------------------------------------------------------------
extern "C" void kernel_launch(void* const* d_in, const int* in_sizes, int n_in,
                              void* d_out, int out_size)
{
    const float* l        = (const float*)d_in[0];
    const float* ab       = (const float*)d_in[1];
    const float* ori      = (const float*)d_in[2];
    const float* comp     = (const float*)d_in[3];
    const int*   y        = (const int*)  d_in[4];
    const int*   idx      = (const int*)  d_in[5];
    const float* mem_l    = (const float*)d_in[6];
    const float* mem_ab   = (const float*)d_in[7];
    const float* mem_ori  = (const float*)d_in[8];
    const float* mem_comp = (const float*)d_in[9];

    float* out       = (float*)d_out;
    float* out_outs  = out;
    float* out_banks = out + OUTS_ELEMS;

    build_kernel<<<(NIDX + 255) / 256, 256>>>(idx, y);
    main_kernel<<<NMEM / 8, 256>>>(l, ab, ori, comp,
                                   mem_l, mem_ab, mem_ori, mem_comp,
                                   idx, out_outs, out_banks);
}

// round 10
// speedup vs baseline: 1.1298x; 1.1298x over previous
#include <cuda_runtime.h>
#include <math.h>

#define Bv    128
#define Dv    128
#define NMEM  200000
#define K1v   2048
#define INV_T (1.0f / 0.07f)

#define OUTS_ELEMS  (6LL * Bv * K1v)
#define MEM_ELEMS   ((long long)NMEM * Dv)
#define NIDX        (Bv * K1v)          // 262144
#define SLOTS       12
#define OVER_CAP    65536

// -------- device scratch (static; no allocations) --------
__device__ int g_count[NMEM];
__device__ int g_owner[NMEM];
__device__ int g_slots[(long long)NMEM * SLOTS];
__device__ int g_over [OVER_CAP];
__device__ int g_nover;

// ---------------------------------------------------------------------------
// Kernel 0: clear scratch (count=0, owner=-1, nover=0), vectorized int4.
// ---------------------------------------------------------------------------
__global__ void clear_kernel()
{
    const int i = blockIdx.x * blockDim.x + threadIdx.x;
    if (i < NMEM / 4) {
        reinterpret_cast<int4*>(g_count)[i] = make_int4(0, 0, 0, 0);
        reinterpret_cast<int4*>(g_owner)[i] = make_int4(-1, -1, -1, -1);
    }
    if (i == 0) g_nover = 0;
}

// ---------------------------------------------------------------------------
// Kernel 1: build inverse map (row -> flat idx positions) + owner map for EMA
// ---------------------------------------------------------------------------
__global__ void build_kernel(const int* __restrict__ idx,
                             const int* __restrict__ y)
{
    const int tid = blockIdx.x * blockDim.x + threadIdx.x;
    if (tid < NIDX) {
        const int row = idx[tid];
        const int pos = atomicAdd(&g_count[row], 1);
        if (pos < SLOTS) g_slots[(long long)row * SLOTS + pos] = tid;
        else {
            const int o = atomicAdd(&g_nover, 1);
            if (o < OVER_CAP) g_over[o] = tid;
        }
    }
    // owner map: last occurrence of y wins (jnp .at[y].set semantics)
    if (tid < Bv) {
        const int yi = y[tid];
        bool last = true;
        for (int j = tid + 1; j < Bv; ++j)
            if (y[j] == yi) { last = false; break; }
        if (last) g_owner[yi] = tid;
    }
}

// ---------------------------------------------------------------------------
// Kernel 2 (main): single streaming pass over all bank rows.
// One warp per row. Front batch: 4x LDG.128 + metadata + slot0 prefetch,
// all unconditional, before any branch or store.
// __launch_bounds__(256, 6): cap regs ~42 -> 6 blocks/SM for latency hiding.
// ---------------------------------------------------------------------------
__global__ __launch_bounds__(256, 6) void main_kernel(
    const float* __restrict__ l,
    const float* __restrict__ ab,
    const float* __restrict__ ori,
    const float* __restrict__ comp,
    const float* __restrict__ mem_l,
    const float* __restrict__ mem_ab,
    const float* __restrict__ mem_ori,
    const float* __restrict__ mem_comp,
    const int*   __restrict__ idx,
    float* __restrict__ outs,
    float* __restrict__ out_banks)
{
    const int warp = threadIdx.x >> 5;
    const int lane = threadIdx.x & 31;
    const long long gw = (long long)blockIdx.x * 8 + warp;   // 0..199999
    const long long r  = gw;

    // ---- front batch: all independent loads, no branches ----
    const float4 wl  = reinterpret_cast<const float4*>(mem_l    + r * Dv)[lane];
    const float4 wab = reinterpret_cast<const float4*>(mem_ab   + r * Dv)[lane];
    const float4 wor = reinterpret_cast<const float4*>(mem_ori  + r * Dv)[lane];
    const float4 wco = reinterpret_cast<const float4*>(mem_comp + r * Dv)[lane];

    const int owner = g_owner[r];
    const int cnt   = g_count[r];
    const int ent0  = g_slots[r * SLOTS];   // prefetch slot 0 (always valid memory)

    // ---- write output banks: plain copy, or EMA-updated row ----
    if (owner < 0) {
        reinterpret_cast<float4*>(out_banks + 0 * MEM_ELEMS + r * Dv)[lane] = wl;
        reinterpret_cast<float4*>(out_banks + 1 * MEM_ELEMS + r * Dv)[lane] = wab;
        reinterpret_cast<float4*>(out_banks + 2 * MEM_ELEMS + r * Dv)[lane] = wor;
        reinterpret_cast<float4*>(out_banks + 3 * MEM_ELEMS + r * Dv)[lane] = wco;
    } else {
        const float* vsrc[4] = {l, ab, ori, comp};
        const float4 wsrc[4] = {wl, wab, wor, wco};
        #pragma unroll
        for (int m = 0; m < 4; ++m) {
            const float4 v = reinterpret_cast<const float4*>(vsrc[m] + owner * Dv)[lane];
            float4 p;
            p.x = wsrc[m].x * 0.5f + v.x * 0.5f;
            p.y = wsrc[m].y * 0.5f + v.y * 0.5f;
            p.z = wsrc[m].z * 0.5f + v.z * 0.5f;
            p.w = wsrc[m].w * 0.5f + v.w * 0.5f;
            float sq = p.x * p.x + p.y * p.y + p.z * p.z + p.w * p.w;
            #pragma unroll
            for (int off = 16; off > 0; off >>= 1)
                sq += __shfl_xor_sync(0xFFFFFFFFu, sq, off);
            const float inv = rsqrtf(sq);
            p.x *= inv; p.y *= inv; p.z *= inv; p.w *= inv;
            reinterpret_cast<float4*>(out_banks + (long long)m * MEM_ELEMS + r * Dv)[lane] = p;
        }
    }

    // ---- dot products for every (b,k) referencing this row ----
    const int nent = cnt < SLOTS ? cnt : SLOTS;
    for (int e = 0; e < nent; ++e) {
        const int ent = (e == 0) ? ent0 : g_slots[r * SLOTS + e];
        const int b   = ent >> 11;          // ent / K1v
        const int k   = ent & (K1v - 1);

        const float4 vl  = __ldg(reinterpret_cast<const float4*>(l    + b * Dv) + lane);
        const float4 vab = __ldg(reinterpret_cast<const float4*>(ab   + b * Dv) + lane);
        const float4 vor = __ldg(reinterpret_cast<const float4*>(ori  + b * Dv) + lane);
        const float4 vco = __ldg(reinterpret_cast<const float4*>(comp + b * Dv) + lane);

        float s0 = wor.x*vl.x  + wor.y*vl.y  + wor.z*vl.z  + wor.w*vl.w;
        float s1 = wl.x *vab.x + wl.y *vab.y + wl.z *vab.z + wl.w *vab.w;
        float s2 = wab.x*vor.x + wab.y*vor.y + wab.z*vor.z + wab.w*vor.w;
        float s3 = wco.x*vab.x + wco.y*vab.y + wco.z*vab.z + wco.w*vab.w;
        float s4 = wco.x*vl.x  + wco.y*vl.y  + wco.z*vl.z  + wco.w*vl.w;
        float s5 = wor.x*vco.x + wor.y*vco.y + wor.z*vco.z + wor.w*vco.w;

        #pragma unroll
        for (int off = 16; off > 0; off >>= 1) {
            s0 += __shfl_xor_sync(0xFFFFFFFFu, s0, off);
            s1 += __shfl_xor_sync(0xFFFFFFFFu, s1, off);
            s2 += __shfl_xor_sync(0xFFFFFFFFu, s2, off);
            s3 += __shfl_xor_sync(0xFFFFFFFFu, s3, off);
            s4 += __shfl_xor_sync(0xFFFFFFFFu, s4, off);
            s5 += __shfl_xor_sync(0xFFFFFFFFu, s5, off);
        }
        if (lane == 0) {
            const long long base   = (long long)b * K1v + k;
            const long long stride = (long long)Bv * K1v;
            outs[0 * stride + base] = s0 * INV_T;
            outs[1 * stride + base] = s1 * INV_T;
            outs[2 * stride + base] = s2 * INV_T;
            outs[3 * stride + base] = s3 * INV_T;
            outs[4 * stride + base] = s4 * INV_T;
            outs[5 * stride + base] = s5 * INV_T;
        }
    }

    // ---- overflow entries (vanishingly rare): gather-style ----
    const int nover = g_nover;
    if (gw < nover) {
        const int ent = g_over[gw];
        const int b   = ent >> 11;
        const int k   = ent & (K1v - 1);
        const long long row = idx[ent];

        const float4 ol  = reinterpret_cast<const float4*>(mem_l    + row * Dv)[lane];
        const float4 oab = reinterpret_cast<const float4*>(mem_ab   + row * Dv)[lane];
        const float4 oor = reinterpret_cast<const float4*>(mem_ori  + row * Dv)[lane];
        const float4 oco = reinterpret_cast<const float4*>(mem_comp + row * Dv)[lane];

        const float4 vl  = __ldg(reinterpret_cast<const float4*>(l    + b * Dv) + lane);
        const float4 vab = __ldg(reinterpret_cast<const float4*>(ab   + b * Dv) + lane);
        const float4 vor = __ldg(reinterpret_cast<const float4*>(ori  + b * Dv) + lane);
        const float4 vco = __ldg(reinterpret_cast<const float4*>(comp + b * Dv) + lane);

        float s0 = oor.x*vl.x  + oor.y*vl.y  + oor.z*vl.z  + oor.w*vl.w;
        float s1 = ol.x *vab.x + ol.y *vab.y + ol.z *vab.z + ol.w *vab.w;
        float s2 = oab.x*vor.x + oab.y*vor.y + oab.z*vor.z + oab.w*vor.w;
        float s3 = oco.x*vab.x + oco.y*vab.y + oco.z*vab.z + oco.w*vab.w;
        float s4 = oco.x*vl.x  + oco.y*vl.y  + oco.z*vl.z  + oco.w*vl.w;
        float s5 = oor.x*vco.x + oor.y*vco.y + oor.z*vco.z + oor.w*vco.w;

        #pragma unroll
        for (int off = 16; off > 0; off >>= 1) {
            s0 += __shfl_xor_sync(0xFFFFFFFFu, s0, off);
            s1 += __shfl_xor_sync(0xFFFFFFFFu, s1, off);
            s2 += __shfl_xor_sync(0xFFFFFFFFu, s2, off);
            s3 += __shfl_xor_sync(0xFFFFFFFFu, s3, off);
            s4 += __shfl_xor_sync(0xFFFFFFFFu, s4, off);
            s5 += __shfl_xor_sync(0xFFFFFFFFu, s5, off);
        }
        if (lane == 0) {
            const long long base   = (long long)b * K1v + k;
            const long long stride = (long long)Bv * K1v;
            outs[0 * stride + base] = s0 * INV_T;
            outs[1 * stride + base] = s1 * INV_T;
            outs[2 * stride + base] = s2 * INV_T;
            outs[3 * stride + base] = s3 * INV_T;
            outs[4 * stride + base] = s4 * INV_T;
            outs[5 * stride + base] = s5 * INV_T;
        }
    }
}

// ---------------------------------------------------------------------------
extern "C" void kernel_launch(void* const* d_in, const int* in_sizes, int n_in,
                              void* d_out, int out_size)
{
    const float* l        = (const float*)d_in[0];
    const float* ab       = (const float*)d_in[1];
    const float* ori      = (const float*)d_in[2];
    const float* comp     = (const float*)d_in[3];
    const int*   y        = (const int*)  d_in[4];
    const int*   idx      = (const int*)  d_in[5];
    const float* mem_l    = (const float*)d_in[6];
    const float* mem_ab   = (const float*)d_in[7];
    const float* mem_ori  = (const float*)d_in[8];
    const float* mem_comp = (const float*)d_in[9];

    float* out       = (float*)d_out;
    float* out_outs  = out;
    float* out_banks = out + OUTS_ELEMS;

    clear_kernel<<<(NMEM / 4 + 255) / 256, 256>>>();
    build_kernel<<<(NIDX + 255) / 256, 256>>>(idx, y);
    main_kernel<<<NMEM / 8, 256>>>(l, ab, ori, comp,
                                   mem_l, mem_ab, mem_ori, mem_comp,
                                   idx, out_outs, out_banks);
}

// round 11
// speedup vs baseline: 1.1303x; 1.0004x over previous
#include <cuda_runtime.h>
#include <math.h>

#define Bv    128
#define Dv    128
#define NMEM  200000
#define K1v   2048
#define INV_T (1.0f / 0.07f)

#define OUTS_ELEMS  (6LL * Bv * K1v)
#define MEM_ELEMS   ((long long)NMEM * Dv)
#define NIDX        (Bv * K1v)          // 262144
#define SLOTS       12
#define OVER_CAP    65536

// -------- device scratch (static zero-init == valid empty state) --------
__device__ int g_count[NMEM];                      // 0 at launch start
__device__ int g_owner[NMEM];                      // owner+1; 0 = no owner
__device__ int g_slots[(long long)NMEM * SLOTS];
__device__ int g_over [OVER_CAP];                  // 0 = empty, else ent+1

// ---------------------------------------------------------------------------
// Kernel 1: build inverse map + owner map. Scratch left zeroed by the
// previous launch's main kernel (static zero-init on first call).
// ---------------------------------------------------------------------------
__global__ void build_kernel(const int* __restrict__ idx,
                             const int* __restrict__ y)
{
    const int tid = blockIdx.x * blockDim.x + threadIdx.x;
    if (tid < NIDX) {
        const int row = idx[tid];
        const int pos = atomicAdd(&g_count[row], 1);
        if (pos < SLOTS) {
            g_slots[(long long)row * SLOTS + pos] = tid;
        } else {
            // astronomically rare (P(count>12) ~ 1e-9): CAS-claim a sentinel slot
            for (int s = 0; s < OVER_CAP; ++s)
                if (atomicCAS(&g_over[s], 0, tid + 1) == 0) break;
        }
    }
    // owner map: last occurrence of y wins (jnp .at[y].set semantics)
    if (tid < Bv) {
        const int yi = y[tid];
        bool last = true;
        for (int j = tid + 1; j < Bv; ++j)
            if (y[j] == yi) { last = false; break; }
        if (last) g_owner[yi] = tid + 1;
    }
}

// ---------------------------------------------------------------------------
// Kernel 2 (main): single streaming pass over all bank rows.
// One warp per row. Front batch: 4x LDG.128 + metadata + slot0 prefetch,
// all unconditional, before any branch or store.
// Metadata self-clean at the VERY END (after all loads have issued).
// ---------------------------------------------------------------------------
__global__ __launch_bounds__(256, 6) void main_kernel(
    const float* __restrict__ l,
    const float* __restrict__ ab,
    const float* __restrict__ ori,
    const float* __restrict__ comp,
    const float* __restrict__ mem_l,
    const float* __restrict__ mem_ab,
    const float* __restrict__ mem_ori,
    const float* __restrict__ mem_comp,
    const int*   __restrict__ idx,
    float* __restrict__ outs,
    float* __restrict__ out_banks)
{
    const int warp = threadIdx.x >> 5;
    const int lane = threadIdx.x & 31;
    const long long gw = (long long)blockIdx.x * 8 + warp;   // 0..199999
    const long long r  = gw;

    // ---- front batch: all independent loads, no branches, no stores ----
    const float4 wl  = reinterpret_cast<const float4*>(mem_l    + r * Dv)[lane];
    const float4 wab = reinterpret_cast<const float4*>(mem_ab   + r * Dv)[lane];
    const float4 wor = reinterpret_cast<const float4*>(mem_ori  + r * Dv)[lane];
    const float4 wco = reinterpret_cast<const float4*>(mem_comp + r * Dv)[lane];

    const int ownerp1 = g_owner[r];
    const int cnt     = g_count[r];
    const int ent0    = g_slots[r * SLOTS];   // prefetch slot 0 (always valid)

    const int owner = ownerp1 - 1;

    // ---- write output banks: plain copy, or EMA-updated row ----
    if (owner < 0) {
        reinterpret_cast<float4*>(out_banks + 0 * MEM_ELEMS + r * Dv)[lane] = wl;
        reinterpret_cast<float4*>(out_banks + 1 * MEM_ELEMS + r * Dv)[lane] = wab;
        reinterpret_cast<float4*>(out_banks + 2 * MEM_ELEMS + r * Dv)[lane] = wor;
        reinterpret_cast<float4*>(out_banks + 3 * MEM_ELEMS + r * Dv)[lane] = wco;
    } else {
        const float* vsrc[4] = {l, ab, ori, comp};
        const float4 wsrc[4] = {wl, wab, wor, wco};
        #pragma unroll
        for (int m = 0; m < 4; ++m) {
            const float4 v = reinterpret_cast<const float4*>(vsrc[m] + owner * Dv)[lane];
            float4 p;
            p.x = wsrc[m].x * 0.5f + v.x * 0.5f;
            p.y = wsrc[m].y * 0.5f + v.y * 0.5f;
            p.z = wsrc[m].z * 0.5f + v.z * 0.5f;
            p.w = wsrc[m].w * 0.5f + v.w * 0.5f;
            float sq = p.x * p.x + p.y * p.y + p.z * p.z + p.w * p.w;
            #pragma unroll
            for (int off = 16; off > 0; off >>= 1)
                sq += __shfl_xor_sync(0xFFFFFFFFu, sq, off);
            const float inv = rsqrtf(sq);
            p.x *= inv; p.y *= inv; p.z *= inv; p.w *= inv;
            reinterpret_cast<float4*>(out_banks + (long long)m * MEM_ELEMS + r * Dv)[lane] = p;
        }
    }

    // ---- dot products for every (b,k) referencing this row ----
    const int nent = cnt < SLOTS ? cnt : SLOTS;
    for (int e = 0; e < nent; ++e) {
        const int ent = (e == 0) ? ent0 : g_slots[r * SLOTS + e];
        const int b   = ent >> 11;          // ent / K1v
        const int k   = ent & (K1v - 1);

        const float4 vl  = __ldg(reinterpret_cast<const float4*>(l    + b * Dv) + lane);
        const float4 vab = __ldg(reinterpret_cast<const float4*>(ab   + b * Dv) + lane);
        const float4 vor = __ldg(reinterpret_cast<const float4*>(ori  + b * Dv) + lane);
        const float4 vco = __ldg(reinterpret_cast<const float4*>(comp + b * Dv) + lane);

        float s0 = wor.x*vl.x  + wor.y*vl.y  + wor.z*vl.z  + wor.w*vl.w;
        float s1 = wl.x *vab.x + wl.y *vab.y + wl.z *vab.z + wl.w *vab.w;
        float s2 = wab.x*vor.x + wab.y*vor.y + wab.z*vor.z + wab.w*vor.w;
        float s3 = wco.x*vab.x + wco.y*vab.y + wco.z*vab.z + wco.w*vab.w;
        float s4 = wco.x*vl.x  + wco.y*vl.y  + wco.z*vl.z  + wco.w*vl.w;
        float s5 = wor.x*vco.x + wor.y*vco.y + wor.z*vco.z + wor.w*vco.w;

        #pragma unroll
        for (int off = 16; off > 0; off >>= 1) {
            s0 += __shfl_xor_sync(0xFFFFFFFFu, s0, off);
            s1 += __shfl_xor_sync(0xFFFFFFFFu, s1, off);
            s2 += __shfl_xor_sync(0xFFFFFFFFu, s2, off);
            s3 += __shfl_xor_sync(0xFFFFFFFFu, s3, off);
            s4 += __shfl_xor_sync(0xFFFFFFFFu, s4, off);
            s5 += __shfl_xor_sync(0xFFFFFFFFu, s5, off);
        }
        if (lane == 0) {
            const long long base   = (long long)b * K1v + k;
            const long long stride = (long long)Bv * K1v;
            outs[0 * stride + base] = s0 * INV_T;
            outs[1 * stride + base] = s1 * INV_T;
            outs[2 * stride + base] = s2 * INV_T;
            outs[3 * stride + base] = s3 * INV_T;
            outs[4 * stride + base] = s4 * INV_T;
            outs[5 * stride + base] = s5 * INV_T;
        }
    }

    // ---- overflow entries (zero-sentinel; astronomically rare) ----
    if (gw < OVER_CAP) {
        const int e = g_over[gw];
        if (e != 0) {
            const int ent = e - 1;
            const int b   = ent >> 11;
            const int k   = ent & (K1v - 1);
            const long long row = idx[ent];

            const float4 ol  = reinterpret_cast<const float4*>(mem_l    + row * Dv)[lane];
            const float4 oab = reinterpret_cast<const float4*>(mem_ab   + row * Dv)[lane];
            const float4 oor = reinterpret_cast<const float4*>(mem_ori  + row * Dv)[lane];
            const float4 oco = reinterpret_cast<const float4*>(mem_comp + row * Dv)[lane];

            const float4 vl  = __ldg(reinterpret_cast<const float4*>(l    + b * Dv) + lane);
            const float4 vab = __ldg(reinterpret_cast<const float4*>(ab   + b * Dv) + lane);
            const float4 vor = __ldg(reinterpret_cast<const float4*>(ori  + b * Dv) + lane);
            const float4 vco = __ldg(reinterpret_cast<const float4*>(comp + b * Dv) + lane);

            float s0 = oor.x*vl.x  + oor.y*vl.y  + oor.z*vl.z  + oor.w*vl.w;
            float s1 = ol.x *vab.x + ol.y *vab.y + ol.z *vab.z + ol.w *vab.w;
            float s2 = oab.x*vor.x + oab.y*vor.y + oab.z*vor.z + oab.w*vor.w;
            float s3 = oco.x*vab.x + oco.y*vab.y + oco.z*vab.z + oco.w*vab.w;
            float s4 = oco.x*vl.x  + oco.y*vl.y  + oco.z*vl.z  + oco.w*vl.w;
            float s5 = oor.x*vco.x + oor.y*vco.y + oor.z*vco.z + oor.w*vco.w;

            #pragma unroll
            for (int off = 16; off > 0; off >>= 1) {
                s0 += __shfl_xor_sync(0xFFFFFFFFu, s0, off);
                s1 += __shfl_xor_sync(0xFFFFFFFFu, s1, off);
                s2 += __shfl_xor_sync(0xFFFFFFFFu, s2, off);
                s3 += __shfl_xor_sync(0xFFFFFFFFu, s3, off);
                s4 += __shfl_xor_sync(0xFFFFFFFFu, s4, off);
                s5 += __shfl_xor_sync(0xFFFFFFFFu, s5, off);
            }
            if (lane == 0) {
                const long long base   = (long long)b * K1v + k;
                const long long stride = (long long)Bv * K1v;
                outs[0 * stride + base] = s0 * INV_T;
                outs[1 * stride + base] = s1 * INV_T;
                outs[2 * stride + base] = s2 * INV_T;
                outs[3 * stride + base] = s3 * INV_T;
                outs[4 * stride + base] = s4 * INV_T;
                outs[5 * stride + base] = s5 * INV_T;
                g_over[gw] = 0;               // reset used sentinel
            }
        }
    }

    // ---- self-clean for next launch (VERY END: after all loads issued) ----
    if (lane == 0) {
        g_count[r] = 0;
        g_owner[r] = 0;
    }
}

// ---------------------------------------------------------------------------
extern "C" void kernel_launch(void* const* d_in, const int* in_sizes, int n_in,
                              void* d_out, int out_size)
{
    const float* l        = (const float*)d_in[0];
    const float* ab       = (const float*)d_in[1];
    const float* ori      = (const float*)d_in[2];
    const float* comp     = (const float*)d_in[3];
    const int*   y        = (const int*)  d_in[4];
    const int*   idx      = (const int*)  d_in[5];
    const float* mem_l    = (const float*)d_in[6];
    const float* mem_ab   = (const float*)d_in[7];
    const float* mem_ori  = (const float*)d_in[8];
    const float* mem_comp = (const float*)d_in[9];

    float* out       = (float*)d_out;
    float* out_outs  = out;
    float* out_banks = out + OUTS_ELEMS;

    build_kernel<<<(NIDX + 255) / 256, 256>>>(idx, y);
    main_kernel<<<NMEM / 8, 256>>>(l, ab, ori, comp,
                                   mem_l, mem_ab, mem_ori, mem_comp,
                                   idx, out_outs, out_banks);
}

// round 12
// speedup vs baseline: 1.1790x; 1.0431x over previous
#include <cuda_runtime.h>
#include <math.h>

#define Bv    128
#define Dv    128
#define NMEM  200000
#define K1v   2048
#define INV_T (1.0f / 0.07f)

#define OUTS_ELEMS  (6LL * Bv * K1v)
#define MEM_ELEMS   ((long long)NMEM * Dv)
#define NIDX        (Bv * K1v)          // 262144
#define SLOTS       12
#define OVER_CAP    65536

// -------- device scratch (static zero-init == valid empty state) --------
// g_cw[r]: bits [0:24) = count (atomicAdd), bits [24:32) = owner+1 (atomicOr).
// count <= 262144 < 2^20, owner+1 <= 128 < 2^8 -> no overflow across fields.
__device__ unsigned int g_cw[NMEM];
__device__ int g_slots[(long long)NMEM * SLOTS];
__device__ int g_over [OVER_CAP];                  // 0 = empty, else ent+1

// ---------------------------------------------------------------------------
// Kernel 1: build inverse map + owner map. Scratch left zeroed by the
// previous launch's main kernel (static zero-init on first call).
// ---------------------------------------------------------------------------
__global__ void build_kernel(const int* __restrict__ idx,
                             const int* __restrict__ y)
{
    const int tid = blockIdx.x * blockDim.x + threadIdx.x;
    if (tid < NIDX) {
        const int row = idx[tid];
        const unsigned int old = atomicAdd(&g_cw[row], 1u);
        const int pos = (int)(old & 0xFFFFFFu);
        if (pos < SLOTS) {
            g_slots[(long long)row * SLOTS + pos] = tid;
        } else {
            // astronomically rare (P(count>12) ~ 1e-9): CAS-claim a sentinel slot
            for (int s = 0; s < OVER_CAP; ++s)
                if (atomicCAS(&g_over[s], 0, tid + 1) == 0) break;
        }
    }
    // owner map: last occurrence of y wins (jnp .at[y].set semantics)
    if (tid < Bv) {
        const int yi = y[tid];
        bool last = true;
        for (int j = tid + 1; j < Bv; ++j)
            if (y[j] == yi) { last = false; break; }
        if (last) atomicOr(&g_cw[yi], (unsigned int)(tid + 1) << 24);
    }
}

// ---------------------------------------------------------------------------
// Kernel 2 (main): single streaming pass over all bank rows.
// One warp per row. Front batch: 4x LDG.128 (evict-first) + packed metadata
// + slot0 prefetch, all unconditional, before any branch or store.
// Bank writes are __stcs (evict-first) to keep L2 for outs + query vectors.
// Metadata self-clean at the VERY END (after all loads have issued).
// ---------------------------------------------------------------------------
__global__ __launch_bounds__(256, 6) void main_kernel(
    const float* __restrict__ l,
    const float* __restrict__ ab,
    const float* __restrict__ ori,
    const float* __restrict__ comp,
    const float* __restrict__ mem_l,
    const float* __restrict__ mem_ab,
    const float* __restrict__ mem_ori,
    const float* __restrict__ mem_comp,
    const int*   __restrict__ idx,
    float* __restrict__ outs,
    float* __restrict__ out_banks)
{
    const int warp = threadIdx.x >> 5;
    const int lane = threadIdx.x & 31;
    const long long gw = (long long)blockIdx.x * 8 + warp;   // 0..199999
    const long long r  = gw;

    // ---- front batch: all independent loads, no branches, no stores ----
    const float4 wl  = __ldcs(reinterpret_cast<const float4*>(mem_l    + r * Dv) + lane);
    const float4 wab = __ldcs(reinterpret_cast<const float4*>(mem_ab   + r * Dv) + lane);
    const float4 wor = __ldcs(reinterpret_cast<const float4*>(mem_ori  + r * Dv) + lane);
    const float4 wco = __ldcs(reinterpret_cast<const float4*>(mem_comp + r * Dv) + lane);

    const unsigned int cw = g_cw[r];
    const int ent0 = g_slots[r * SLOTS];   // prefetch slot 0 (always valid)

    const int cnt   = (int)(cw & 0xFFFFFFu);
    const int owner = (int)(cw >> 24) - 1;

    // ---- write output banks: plain copy, or EMA-updated row ----
    if (owner < 0) {
        __stcs(reinterpret_cast<float4*>(out_banks + 0 * MEM_ELEMS + r * Dv) + lane, wl);
        __stcs(reinterpret_cast<float4*>(out_banks + 1 * MEM_ELEMS + r * Dv) + lane, wab);
        __stcs(reinterpret_cast<float4*>(out_banks + 2 * MEM_ELEMS + r * Dv) + lane, wor);
        __stcs(reinterpret_cast<float4*>(out_banks + 3 * MEM_ELEMS + r * Dv) + lane, wco);
    } else {
        const float* vsrc[4] = {l, ab, ori, comp};
        const float4 wsrc[4] = {wl, wab, wor, wco};
        #pragma unroll
        for (int m = 0; m < 4; ++m) {
            const float4 v = reinterpret_cast<const float4*>(vsrc[m] + owner * Dv)[lane];
            float4 p;
            p.x = wsrc[m].x * 0.5f + v.x * 0.5f;
            p.y = wsrc[m].y * 0.5f + v.y * 0.5f;
            p.z = wsrc[m].z * 0.5f + v.z * 0.5f;
            p.w = wsrc[m].w * 0.5f + v.w * 0.5f;
            float sq = p.x * p.x + p.y * p.y + p.z * p.z + p.w * p.w;
            #pragma unroll
            for (int off = 16; off > 0; off >>= 1)
                sq += __shfl_xor_sync(0xFFFFFFFFu, sq, off);
            const float inv = rsqrtf(sq);
            p.x *= inv; p.y *= inv; p.z *= inv; p.w *= inv;
            __stcs(reinterpret_cast<float4*>(out_banks + (long long)m * MEM_ELEMS + r * Dv) + lane, p);
        }
    }

    // ---- dot products for every (b,k) referencing this row ----
    const int nent = cnt < SLOTS ? cnt : SLOTS;
    for (int e = 0; e < nent; ++e) {
        const int ent = (e == 0) ? ent0 : g_slots[r * SLOTS + e];
        const int b   = ent >> 11;          // ent / K1v
        const int k   = ent & (K1v - 1);

        const float4 vl  = __ldg(reinterpret_cast<const float4*>(l    + b * Dv) + lane);
        const float4 vab = __ldg(reinterpret_cast<const float4*>(ab   + b * Dv) + lane);
        const float4 vor = __ldg(reinterpret_cast<const float4*>(ori  + b * Dv) + lane);
        const float4 vco = __ldg(reinterpret_cast<const float4*>(comp + b * Dv) + lane);

        float s0 = wor.x*vl.x  + wor.y*vl.y  + wor.z*vl.z  + wor.w*vl.w;
        float s1 = wl.x *vab.x + wl.y *vab.y + wl.z *vab.z + wl.w *vab.w;
        float s2 = wab.x*vor.x + wab.y*vor.y + wab.z*vor.z + wab.w*vor.w;
        float s3 = wco.x*vab.x + wco.y*vab.y + wco.z*vab.z + wco.w*vab.w;
        float s4 = wco.x*vl.x  + wco.y*vl.y  + wco.z*vl.z  + wco.w*vl.w;
        float s5 = wor.x*vco.x + wor.y*vco.y + wor.z*vco.z + wor.w*vco.w;

        #pragma unroll
        for (int off = 16; off > 0; off >>= 1) {
            s0 += __shfl_xor_sync(0xFFFFFFFFu, s0, off);
            s1 += __shfl_xor_sync(0xFFFFFFFFu, s1, off);
            s2 += __shfl_xor_sync(0xFFFFFFFFu, s2, off);
            s3 += __shfl_xor_sync(0xFFFFFFFFu, s3, off);
            s4 += __shfl_xor_sync(0xFFFFFFFFu, s4, off);
            s5 += __shfl_xor_sync(0xFFFFFFFFu, s5, off);
        }
        if (lane == 0) {
            const long long base   = (long long)b * K1v + k;
            const long long stride = (long long)Bv * K1v;
            outs[0 * stride + base] = s0 * INV_T;
            outs[1 * stride + base] = s1 * INV_T;
            outs[2 * stride + base] = s2 * INV_T;
            outs[3 * stride + base] = s3 * INV_T;
            outs[4 * stride + base] = s4 * INV_T;
            outs[5 * stride + base] = s5 * INV_T;
        }
    }

    // ---- overflow entries (zero-sentinel; astronomically rare) ----
    if (gw < OVER_CAP) {
        const int e = g_over[gw];
        if (e != 0) {
            const int ent = e - 1;
            const int b   = ent >> 11;
            const int k   = ent & (K1v - 1);
            const long long row = idx[ent];

            const float4 ol  = reinterpret_cast<const float4*>(mem_l    + row * Dv)[lane];
            const float4 oab = reinterpret_cast<const float4*>(mem_ab   + row * Dv)[lane];
            const float4 oor = reinterpret_cast<const float4*>(mem_ori  + row * Dv)[lane];
            const float4 oco = reinterpret_cast<const float4*>(mem_comp + row * Dv)[lane];

            const float4 vl  = __ldg(reinterpret_cast<const float4*>(l    + b * Dv) + lane);
            const float4 vab = __ldg(reinterpret_cast<const float4*>(ab   + b * Dv) + lane);
            const float4 vor = __ldg(reinterpret_cast<const float4*>(ori  + b * Dv) + lane);
            const float4 vco = __ldg(reinterpret_cast<const float4*>(comp + b * Dv) + lane);

            float s0 = oor.x*vl.x  + oor.y*vl.y  + oor.z*vl.z  + oor.w*vl.w;
            float s1 = ol.x *vab.x + ol.y *vab.y + ol.z *vab.z + ol.w *vab.w;
            float s2 = oab.x*vor.x + oab.y*vor.y + oab.z*vor.z + oab.w*vor.w;
            float s3 = oco.x*vab.x + oco.y*vab.y + oco.z*vab.z + oco.w*vab.w;
            float s4 = oco.x*vl.x  + oco.y*vl.y  + oco.z*vl.z  + oco.w*vl.w;
            float s5 = oor.x*vco.x + oor.y*vco.y + oor.z*vco.z + oor.w*vco.w;

            #pragma unroll
            for (int off = 16; off > 0; off >>= 1) {
                s0 += __shfl_xor_sync(0xFFFFFFFFu, s0, off);
                s1 += __shfl_xor_sync(0xFFFFFFFFu, s1, off);
                s2 += __shfl_xor_sync(0xFFFFFFFFu, s2, off);
                s3 += __shfl_xor_sync(0xFFFFFFFFu, s3, off);
                s4 += __shfl_xor_sync(0xFFFFFFFFu, s4, off);
                s5 += __shfl_xor_sync(0xFFFFFFFFu, s5, off);
            }
            if (lane == 0) {
                const long long base   = (long long)b * K1v + k;
                const long long stride = (long long)Bv * K1v;
                outs[0 * stride + base] = s0 * INV_T;
                outs[1 * stride + base] = s1 * INV_T;
                outs[2 * stride + base] = s2 * INV_T;
                outs[3 * stride + base] = s3 * INV_T;
                outs[4 * stride + base] = s4 * INV_T;
                outs[5 * stride + base] = s5 * INV_T;
                g_over[gw] = 0;               // reset used sentinel
            }
        }
    }

    // ---- self-clean for next launch (VERY END: after all loads issued) ----
    if (lane == 0) g_cw[r] = 0u;
}

// ---------------------------------------------------------------------------
extern "C" void kernel_launch(void* const* d_in, const int* in_sizes, int n_in,
                              void* d_out, int out_size)
{
    const float* l        = (const float*)d_in[0];
    const float* ab       = (const float*)d_in[1];
    const float* ori      = (const float*)d_in[2];
    const float* comp     = (const float*)d_in[3];
    const int*   y        = (const int*)  d_in[4];
    const int*   idx      = (const int*)  d_in[5];
    const float* mem_l    = (const float*)d_in[6];
    const float* mem_ab   = (const float*)d_in[7];
    const float* mem_ori  = (const float*)d_in[8];
    const float* mem_comp = (const float*)d_in[9];

    float* out       = (float*)d_out;
    float* out_outs  = out;
    float* out_banks = out + OUTS_ELEMS;

    build_kernel<<<(NIDX + 255) / 256, 256>>>(idx, y);
    main_kernel<<<NMEM / 8, 256>>>(l, ab, ori, comp,
                                   mem_l, mem_ab, mem_ori, mem_comp,
                                   idx, out_outs, out_banks);
}